// round 1
// baseline (speedup 1.0000x reference)
#include <cuda_runtime.h>
#include <math.h>

#define N_PTS 262144
#define MT 32            // points per block tile
#define STR 34           // shared row stride in floats (pad to break bank conflicts)

typedef unsigned long long u64;

__device__ __forceinline__ u64 pack2(float x, float y) {
    u64 r; asm("mov.b64 %0, {%1,%2};" : "=l"(r) : "f"(x), "f"(y)); return r;
}
__device__ __forceinline__ void ffma2(u64& d, u64 a, u64 b) {
    asm("fma.rn.f32x2 %0, %1, %2, %0;" : "+l"(d) : "l"(a), "l"(b));
}
__device__ __forceinline__ float2 u2f(u64 v) {
    float2 r; asm("mov.b64 {%0,%1}, %2;" : "=f"(r.x), "=f"(r.y) : "l"(v)); return r;
}

struct Params {
    const float *pos, *dir, *Win, *bin;
    const float *Wh[7];
    const float *bh[7];
    const float *Wout, *bout, *Wr1, *br1, *Wr2, *br2;
    float* out;
};

// Block-tile GEMM layer: dst[n][m] = act( sum_k src[k][m] * W[k][n] + bias[n] )
// src buffers are SMEM in [k][m] layout with stride STR. Supports concat input
// (s1: K1 rows, s2: K2 rows -> W rows K1..K1+K2-1). Thread (tm,tn) computes
// 8 points (m0=tm*8) x NSUB neurons (n0=tn*NSUB); NOUT = 64*NSUB.
// WS = weight row stride (= layer's fan_out).
template<int WS, int NSUB, bool RELU>
__device__ __forceinline__ void gemm_layer(
    const float* __restrict__ W, const float* __restrict__ bias,
    const float* __restrict__ s1, int K1,
    const float* __restrict__ s2, int K2,
    float* __restrict__ dst, int tm, int tn)
{
    u64 acc[NSUB][4];
#pragma unroll
    for (int j = 0; j < NSUB; j++)
#pragma unroll
        for (int i = 0; i < 4; i++) acc[j][i] = 0ull;

    const int m0 = tm * 8;
    const int n0 = tn * NSUB;

    auto body = [&](const float* __restrict__ src, int kbase, int K) {
#pragma unroll 4
        for (int k = 0; k < K; k++) {
            const float* wr = W + (size_t)(kbase + k) * WS + n0;
            float w[NSUB];
            if constexpr (NSUB == 4 && (WS % 4) == 0) {
                float4 wv = *(const float4*)wr;
                w[0] = wv.x; w[1] = wv.y; w[2] = wv.z; w[3] = wv.w;
            } else if constexpr (NSUB == 2 && (WS % 2) == 0) {
                float2 wv = *(const float2*)wr;
                w[0] = wv.x; w[1] = wv.y;
            } else {
#pragma unroll
                for (int j = 0; j < NSUB; j++) w[j] = wr[j];
            }
            u64 w2[NSUB];
#pragma unroll
            for (int j = 0; j < NSUB; j++) w2[j] = pack2(w[j], w[j]);
            u64 h2[4];
#pragma unroll
            for (int i = 0; i < 4; i++)
                h2[i] = *(const u64*)(src + k * STR + m0 + 2 * i);
#pragma unroll
            for (int j = 0; j < NSUB; j++)
#pragma unroll
                for (int i = 0; i < 4; i++) ffma2(acc[j][i], h2[i], w2[j]);
        }
    };
    body(s1, 0, K1);
    if (K2 > 0) body(s2, K1, K2);

#pragma unroll
    for (int j = 0; j < NSUB; j++) {
        float bn = bias[n0 + j];
#pragma unroll
        for (int i = 0; i < 4; i++) {
            float2 v = u2f(acc[j][i]);
            v.x += bn; v.y += bn;
            if (RELU) { v.x = fmaxf(v.x, 0.f); v.y = fmaxf(v.y, 0.f); }
            *(float2*)(dst + (n0 + j) * STR + m0 + 2 * i) = v;
        }
    }
}

__global__ void __launch_bounds__(256) nerf_kernel(Params p)
{
    extern __shared__ float sm[];
    float* A  = sm;                 // 256 * STR
    float* B  = A + 256 * STR;      // 256 * STR
    float* PE = B + 256 * STR;      // 63  * STR
    float* DE = PE + 63 * STR;      // 27  * STR

    const int tid = threadIdx.x;
    const int tm = tid >> 6;        // 0..3 (8-point groups)
    const int tn = tid & 63;        // 0..63 (neuron groups)
    const int g0 = blockIdx.x * MT;

    // ---- Positional / directional encoding into SMEM [k][m] ----
    if (tid < 96) {
        const int m = tid & 31, d = tid >> 5;   // d in 0..2
        float x = p.pos[(g0 + m) * 3 + d];
        PE[d * STR + m] = x;
        float f = 1.f;
#pragma unroll
        for (int q = 0; q < 10; q++) {
            float s, c; sincosf(x * f, &s, &c);
            PE[(3 + 6 * q + d) * STR + m]     = s;
            PE[(3 + 6 * q + 3 + d) * STR + m] = c;
            f *= 2.f;
        }
        float y = p.dir[(g0 + m) * 3 + d];
        DE[d * STR + m] = y;
        f = 1.f;
#pragma unroll
        for (int q = 0; q < 4; q++) {
            float s, c; sincosf(y * f, &s, &c);
            DE[(3 + 6 * q + d) * STR + m]     = s;
            DE[(3 + 6 * q + 3 + d) * STR + m] = c;
            f *= 2.f;
        }
    }
    __syncthreads();

    // ---- Trunk MLP ----
    gemm_layer<256, 4, true >(p.Win,   p.bin,   PE, 63, nullptr, 0, A, tm, tn); __syncthreads();
    gemm_layer<256, 4, true >(p.Wh[0], p.bh[0], A, 256, nullptr, 0, B, tm, tn); __syncthreads();
    gemm_layer<256, 4, true >(p.Wh[1], p.bh[1], B, 256, nullptr, 0, A, tm, tn); __syncthreads();
    gemm_layer<256, 4, true >(p.Wh[2], p.bh[2], A, 256, nullptr, 0, B, tm, tn); __syncthreads();
    gemm_layer<256, 4, true >(p.Wh[3], p.bh[3], B, 256, nullptr, 0, A, tm, tn); __syncthreads();
    gemm_layer<256, 4, true >(p.Wh[4], p.bh[4], A, 256, PE,     63, B, tm, tn); __syncthreads();
    gemm_layer<256, 4, true >(p.Wh[5], p.bh[5], B, 256, nullptr, 0, A, tm, tn); __syncthreads();
    gemm_layer<256, 4, true >(p.Wh[6], p.bh[6], A, 256, nullptr, 0, B, tm, tn); __syncthreads();

    // ---- Output layer: features (cols 0..255, NO relu): B -> A ----
    gemm_layer<257, 4, false>(p.Wout,  p.bout,  B, 256, nullptr, 0, A, tm, tn);
    __syncthreads();

    // ---- Density (column 256 of W_out, relu), reads B ----
    if (tid < 32) {
        const int m = tid;
        float a = p.bout[256];
#pragma unroll 4
        for (int k = 0; k < 256; k++)
            a += B[k * STR + m] * p.Wout[k * 257 + 256];
        p.out[3 * N_PTS + g0 + m] = fmaxf(a, 0.f);
    }
    __syncthreads();

    // ---- RGB head: r1 = relu([features, de] @ W_r1 + b): A(+DE) -> B rows 0..127 ----
    gemm_layer<128, 2, true >(p.Wr1,   p.br1,   A, 256, DE,     27, B, tm, tn);
    __syncthreads();

    // ---- r2 = sigmoid(B(128) @ W_r2 + b): 96 outputs ----
    if (tid < 96) {
        const int m = tid & 31, n = tid >> 5;   // n in 0..2
        float a = p.br2[n];
#pragma unroll 4
        for (int k = 0; k < 128; k++)
            a += B[k * STR + m] * p.Wr2[k * 3 + n];
        p.out[(g0 + m) * 3 + n] = 1.f / (1.f + expf(-a));
    }
}

static const int SMEM_BYTES = (2 * 256 + 63 + 27) * STR * (int)sizeof(float);  // 81872

extern "C" void kernel_launch(void* const* d_in, const int* in_sizes, int n_in,
                              void* d_out, int out_size)
{
    Params p;
    p.pos = (const float*)d_in[0];
    p.dir = (const float*)d_in[1];
    p.Win = (const float*)d_in[2];
    p.bin = (const float*)d_in[3];
    for (int i = 0; i < 7; i++) {
        p.Wh[i] = (const float*)d_in[4 + 2 * i];
        p.bh[i] = (const float*)d_in[5 + 2 * i];
    }
    p.Wout = (const float*)d_in[18];
    p.bout = (const float*)d_in[19];
    p.Wr1  = (const float*)d_in[20];
    p.br1  = (const float*)d_in[21];
    p.Wr2  = (const float*)d_in[22];
    p.br2  = (const float*)d_in[23];
    p.out  = (float*)d_out;

    cudaFuncSetAttribute(nerf_kernel, cudaFuncAttributeMaxDynamicSharedMemorySize, SMEM_BYTES);
    nerf_kernel<<<N_PTS / MT, 256, SMEM_BYTES>>>(p);
}

// round 2
// speedup vs baseline: 1.0034x; 1.0034x over previous
#include <cuda_runtime.h>
#include <math.h>

#define N_PTS 262144
#define MT 32            // points per block tile
#define STR 34           // shared row stride in floats (pad to break bank conflicts)

typedef unsigned long long u64;

__device__ __forceinline__ u64 pack2(float x, float y) {
    u64 r; asm("mov.b64 %0, {%1,%2};" : "=l"(r) : "f"(x), "f"(y)); return r;
}
__device__ __forceinline__ void ffma2(u64& d, u64 a, u64 b) {
    asm("fma.rn.f32x2 %0, %1, %2, %0;" : "+l"(d) : "l"(a), "l"(b));
}
__device__ __forceinline__ float2 u2f(u64 v) {
    float2 r; asm("mov.b64 {%0,%1}, %2;" : "=f"(r.x), "=f"(r.y) : "l"(v)); return r;
}

struct Params {
    const float *pos, *dir, *Win, *bin;
    const float *Wh[7];
    const float *bh[7];
    const float *Wout, *bout, *Wr1, *br1, *Wr2, *br2;
    float* out;
};

// Block-tile GEMM layer: dst[n][m] = act( sum_k src[k][m] * W[k][n] + bias[n] )
// src buffers are SMEM in [k][m] layout with stride STR. Supports concat input
// (s1: K1 rows, s2: K2 rows -> W rows K1..K1+K2-1). Thread (tm,tn) computes
// 8 points (m0=tm*8) x NSUB neurons (n0=tn*NSUB); NOUT = 64*NSUB.
// WS = weight row stride (= layer's fan_out).
template<int WS, int NSUB, bool RELU>
__device__ __forceinline__ void gemm_layer(
    const float* __restrict__ W, const float* __restrict__ bias,
    const float* __restrict__ s1, int K1,
    const float* __restrict__ s2, int K2,
    float* __restrict__ dst, int tm, int tn)
{
    u64 acc[NSUB][4];
#pragma unroll
    for (int j = 0; j < NSUB; j++)
#pragma unroll
        for (int i = 0; i < 4; i++) acc[j][i] = 0ull;

    const int m0 = tm * 8;
    const int n0 = tn * NSUB;

    auto body = [&](const float* __restrict__ src, int kbase, int K) {
#pragma unroll 4
        for (int k = 0; k < K; k++) {
            const float* wr = W + (size_t)(kbase + k) * WS + n0;
            float w[NSUB];
            if constexpr (NSUB == 4 && (WS % 4) == 0) {
                float4 wv = *(const float4*)wr;
                w[0] = wv.x; w[1] = wv.y; w[2] = wv.z; w[3] = wv.w;
            } else if constexpr (NSUB == 2 && (WS % 2) == 0) {
                float2 wv = *(const float2*)wr;
                w[0] = wv.x; w[1] = wv.y;
            } else {
#pragma unroll
                for (int j = 0; j < NSUB; j++) w[j] = wr[j];
            }
            u64 w2[NSUB];
#pragma unroll
            for (int j = 0; j < NSUB; j++) w2[j] = pack2(w[j], w[j]);
            u64 h2[4];
#pragma unroll
            for (int i = 0; i < 4; i++)
                h2[i] = *(const u64*)(src + k * STR + m0 + 2 * i);
#pragma unroll
            for (int j = 0; j < NSUB; j++)
#pragma unroll
                for (int i = 0; i < 4; i++) ffma2(acc[j][i], h2[i], w2[j]);
        }
    };
    body(s1, 0, K1);
    if (K2 > 0) body(s2, K1, K2);

#pragma unroll
    for (int j = 0; j < NSUB; j++) {
        float bn = bias[n0 + j];
#pragma unroll
        for (int i = 0; i < 4; i++) {
            float2 v = u2f(acc[j][i]);
            v.x += bn; v.y += bn;
            if (RELU) { v.x = fmaxf(v.x, 0.f); v.y = fmaxf(v.y, 0.f); }
            *(float2*)(dst + (n0 + j) * STR + m0 + 2 * i) = v;
        }
    }
}

__global__ void __launch_bounds__(256) nerf_kernel(Params p)
{
    extern __shared__ float sm[];
    float* A  = sm;                 // 256 * STR
    float* B  = A + 256 * STR;      // 256 * STR
    float* PE = B + 256 * STR;      // 63  * STR
    float* DE = PE + 63 * STR;      // 27  * STR

    const int tid = threadIdx.x;
    const int tm = tid >> 6;        // 0..3 (8-point groups)
    const int tn = tid & 63;        // 0..63 (neuron groups)
    const int g0 = blockIdx.x * MT;

    // ---- Positional / directional encoding into SMEM [k][m] ----
    if (tid < 96) {
        const int m = tid & 31, d = tid >> 5;   // d in 0..2
        float x = p.pos[(g0 + m) * 3 + d];
        PE[d * STR + m] = x;
        float f = 1.f;
#pragma unroll
        for (int q = 0; q < 10; q++) {
            float s, c; sincosf(x * f, &s, &c);
            PE[(3 + 6 * q + d) * STR + m]     = s;
            PE[(3 + 6 * q + 3 + d) * STR + m] = c;
            f *= 2.f;
        }
        float y = p.dir[(g0 + m) * 3 + d];
        DE[d * STR + m] = y;
        f = 1.f;
#pragma unroll
        for (int q = 0; q < 4; q++) {
            float s, c; sincosf(y * f, &s, &c);
            DE[(3 + 6 * q + d) * STR + m]     = s;
            DE[(3 + 6 * q + 3 + d) * STR + m] = c;
            f *= 2.f;
        }
    }
    __syncthreads();

    // ---- Trunk MLP ----
    gemm_layer<256, 4, true >(p.Win,   p.bin,   PE, 63, nullptr, 0, A, tm, tn); __syncthreads();
    gemm_layer<256, 4, true >(p.Wh[0], p.bh[0], A, 256, nullptr, 0, B, tm, tn); __syncthreads();
    gemm_layer<256, 4, true >(p.Wh[1], p.bh[1], B, 256, nullptr, 0, A, tm, tn); __syncthreads();
    gemm_layer<256, 4, true >(p.Wh[2], p.bh[2], A, 256, nullptr, 0, B, tm, tn); __syncthreads();
    gemm_layer<256, 4, true >(p.Wh[3], p.bh[3], B, 256, nullptr, 0, A, tm, tn); __syncthreads();
    gemm_layer<256, 4, true >(p.Wh[4], p.bh[4], A, 256, PE,     63, B, tm, tn); __syncthreads();
    gemm_layer<256, 4, true >(p.Wh[5], p.bh[5], B, 256, nullptr, 0, A, tm, tn); __syncthreads();
    gemm_layer<256, 4, true >(p.Wh[6], p.bh[6], A, 256, nullptr, 0, B, tm, tn); __syncthreads();

    // ---- Output layer: features (cols 0..255, NO relu): B -> A ----
    gemm_layer<257, 4, false>(p.Wout,  p.bout,  B, 256, nullptr, 0, A, tm, tn);
    __syncthreads();

    // ---- Density (column 256 of W_out, relu), reads B ----
    if (tid < 32) {
        const int m = tid;
        float a = p.bout[256];
#pragma unroll 4
        for (int k = 0; k < 256; k++)
            a += B[k * STR + m] * p.Wout[k * 257 + 256];
        p.out[3 * N_PTS + g0 + m] = fmaxf(a, 0.f);
    }
    __syncthreads();

    // ---- RGB head: r1 = relu([features, de] @ W_r1 + b): A(+DE) -> B rows 0..127 ----
    gemm_layer<128, 2, true >(p.Wr1,   p.br1,   A, 256, DE,     27, B, tm, tn);
    __syncthreads();

    // ---- r2 = sigmoid(B(128) @ W_r2 + b): 96 outputs ----
    if (tid < 96) {
        const int m = tid & 31, n = tid >> 5;   // n in 0..2
        float a = p.br2[n];
#pragma unroll 4
        for (int k = 0; k < 128; k++)
            a += B[k * STR + m] * p.Wr2[k * 3 + n];
        p.out[(g0 + m) * 3 + n] = 1.f / (1.f + expf(-a));
    }
}

static const int SMEM_BYTES = (2 * 256 + 63 + 27) * STR * (int)sizeof(float);  // 81872

extern "C" void kernel_launch(void* const* d_in, const int* in_sizes, int n_in,
                              void* d_out, int out_size)
{
    Params p;
    p.pos = (const float*)d_in[0];
    p.dir = (const float*)d_in[1];
    p.Win = (const float*)d_in[2];
    p.bin = (const float*)d_in[3];
    for (int i = 0; i < 7; i++) {
        p.Wh[i] = (const float*)d_in[4 + 2 * i];
        p.bh[i] = (const float*)d_in[5 + 2 * i];
    }
    p.Wout = (const float*)d_in[18];
    p.bout = (const float*)d_in[19];
    p.Wr1  = (const float*)d_in[20];
    p.br1  = (const float*)d_in[21];
    p.Wr2  = (const float*)d_in[22];
    p.br2  = (const float*)d_in[23];
    p.out  = (float*)d_out;

    cudaFuncSetAttribute(nerf_kernel, cudaFuncAttributeMaxDynamicSharedMemorySize, SMEM_BYTES);
    nerf_kernel<<<N_PTS / MT, 256, SMEM_BYTES>>>(p);
}

// round 7
// speedup vs baseline: 2.9239x; 2.9139x over previous
#include <cuda_runtime.h>
#include <cuda_fp16.h>
#include <stdint.h>
#include <math.h>

typedef uint32_t u32; typedef uint64_t u64; typedef unsigned short u16;

#define N_PTS 262144
#define TOTB 4640

// weight blocks in B-fragment order: block b = 512B: hi lane l at [b*64+l], lo at [b*64+32+l]
__device__ __align__(16) u64 g_w[TOTB * 64];
__device__ float g_dcol[256];

// seg block offsets (layout: Win | Wh0..Wh4 | H4PE | Wh5 | Wh6 | Wout | Wr1 | Wr1de)
#define SEG_WIN  0
#define SEG_H0   128
#define SEG_H4PE 2688
#define SEG_H5   2816
#define SEG_H6   3328
#define SEG_OUT  3840
#define SEG_R1   4352
#define SEG_R1DE 4608

// ---------- fp16 helpers (RNE) ----------
__device__ __forceinline__ u32 f2h(float f) {
    return (u32)__half_as_ushort(__float2half_rn(f));
}
__device__ __forceinline__ float h2f(u32 h) {
    return __half2float(__ushort_as_half((u16)h));
}

__device__ __forceinline__ u32 s2u(const void* p) {
    u32 a;
    asm("{ .reg .u64 t; cvta.to.shared.u64 t, %1; cvt.u32.u64 %0, t; }" : "=r"(a) : "l"(p));
    return a;
}

#define LDMX4(R, addr) \
    asm volatile("ldmatrix.sync.aligned.m8n8.x4.shared.b16 {%0,%1,%2,%3}, [%4];" \
        : "=r"((R)[0]), "=r"((R)[1]), "=r"((R)[2]), "=r"((R)[3]) : "r"(addr))

#define MMA(D, A, b0, b1) \
    asm volatile("mma.sync.aligned.m16n8k16.row.col.f32.f16.f16.f32 " \
        "{%0,%1,%2,%3},{%4,%5,%6,%7},{%8,%9},{%0,%1,%2,%3};" \
        : "+f"((D)[0]), "+f"((D)[1]), "+f"((D)[2]), "+f"((D)[3]) \
        : "r"((A)[0]), "r"((A)[1]), "r"((A)[2]), "r"((A)[3]), "r"(b0), "r"(b1))

// ---------- SMEM layout (bytes) ----------
#define O_AHI  0
#define O_ALO  67584
#define O_PEHI 135168
#define O_PELO 153600
#define O_DEHI 172032
#define O_DELO 182272
#define O_BIAS 192512
#define O_DCOL 193552
#define O_WR2  194576
#define SMEM_TOTAL 196608

// ---------- prep kernel: weights -> fragment order, split hi/lo ----------
struct Seg { const float* src; int rs, kv, nv, NT, start; };
struct PrepP { Seg seg[12]; const float* Wout; };

__global__ void prep_kernel(PrepP pp) {
    int b = blockIdx.x * 8 + (threadIdx.x >> 5);
    int l = threadIdx.x & 31;
    if (blockIdx.x == 0) g_dcol[threadIdx.x] = pp.Wout[threadIdx.x * 257 + 256];
    int si = 0;
#pragma unroll
    for (int i = 1; i < 12; i++) if (b >= pp.seg[i].start) si = i;
    Seg sg = pp.seg[si];
    int rel = b - sg.start;
    int s = rel / sg.NT, tg = rel % sg.NT;
    int n = tg * 8 + (l >> 2);
    u64 hv = 0, lv = 0;
#pragma unroll
    for (int idx = 0; idx < 4; idx++) {
        int r = idx >> 1, j = idx & 1;
        int k = s * 16 + (l & 3) * 2 + r * 8 + j;
        float w = (k < sg.kv && n < sg.nv) ? sg.src[(size_t)k * sg.rs + n] : 0.f;
        u32 hb = f2h(w);
        u32 lb = f2h(w - h2f(hb));
        hv |= (u64)hb << (16 * idx);
        lv |= (u64)lb << (16 * idx);
    }
    g_w[(size_t)b * 64 + l] = hv;
    g_w[(size_t)b * 64 + 32 + l] = lv;
}

// ---------- main kernel ----------
struct Params {
    const float *pos, *dir, *bout, *wr2, *br2;
    const float* bias[10];
    float* out;
};

// MMA over one K-segment. ah_base/al_base: smem addr incl. this thread's row/koff.
template<int NTW>
__device__ __forceinline__ void run_seg(float (&acc)[4][8][4], u32 ah_base, u32 al_base,
    int strideB, int S, int NT, const u64* __restrict__ wseg, int wn, int l)
{
    for (int s = 0; s < S; s++) {
        u32 ah[4][4], al[4][4];
#pragma unroll
        for (int mt = 0; mt < 4; mt++) {
            LDMX4(ah[mt], ah_base + mt * 16 * strideB + s * 32);
            LDMX4(al[mt], al_base + mt * 16 * strideB + s * 32);
        }
        const u64* blk = wseg + (size_t)(s * NT + wn * NTW) * 64 + l;
        u64 wh[NTW], wl[NTW];
#pragma unroll
        for (int t = 0; t < NTW; t++) { wh[t] = blk[t * 64]; wl[t] = blk[t * 64 + 32]; }
#pragma unroll
        for (int t = 0; t < NTW; t++) {
            u32 h0 = (u32)wh[t], h1 = (u32)(wh[t] >> 32);
#pragma unroll
            for (int mt = 0; mt < 4; mt++) MMA(acc[mt][t], ah[mt], h0, h1);
#pragma unroll
            for (int mt = 0; mt < 4; mt++) MMA(acc[mt][t], al[mt], h0, h1);
            u32 l0 = (u32)wl[t], l1 = (u32)(wl[t] >> 32);
#pragma unroll
            for (int mt = 0; mt < 4; mt++) MMA(acc[mt][t], ah[mt], l0, l1);
        }
    }
}

template<int NTW>
__device__ __forceinline__ void epilogue(float (&acc)[4][8][4], u16* HI, u16* LO,
    const float* sbias, bool relu, int wm, int wn, int l)
{
    int cb = wn * NTW * 8 + (l & 3) * 2;
    int rb = wm * 64 + (l >> 2);
#pragma unroll
    for (int mt = 0; mt < 4; mt++)
#pragma unroll
        for (int t = 0; t < NTW; t++)
#pragma unroll
            for (int h = 0; h < 2; h++) {
                int r = rb + mt * 16 + h * 8, c = cb + t * 8;
                float v0 = acc[mt][t][2 * h]     + sbias[c];
                float v1 = acc[mt][t][2 * h + 1] + sbias[c + 1];
                if (relu) { v0 = fmaxf(v0, 0.f); v1 = fmaxf(v1, 0.f); }
                u32 h0 = f2h(v0), h1 = f2h(v1);
                u32 l0 = f2h(v0 - h2f(h0)), l1 = f2h(v1 - h2f(h1));
                *(u32*)&HI[r * 264 + c] = h0 | (h1 << 16);
                *(u32*)&LO[r * 264 + c] = l0 | (l1 << 16);
            }
}

__global__ void __launch_bounds__(256, 1) nerf_mma(Params p)
{
    extern __shared__ char sm[];
    u16* AHI = (u16*)(sm + O_AHI);
    u16* ALO = (u16*)(sm + O_ALO);
    u16* PHI = (u16*)(sm + O_PEHI);
    u16* PLO = (u16*)(sm + O_PELO);
    u16* DHI = (u16*)(sm + O_DEHI);
    u16* DLO = (u16*)(sm + O_DELO);
    float* sbias = (float*)(sm + O_BIAS);
    float* sdcol = (float*)(sm + O_DCOL);
    float* swr2  = (float*)(sm + O_WR2);

    const int tid = threadIdx.x;
    const int l = tid & 31, wid = tid >> 5;
    const int wm = wid >> 2, wn = wid & 3;

    sdcol[tid] = g_dcol[tid];
    for (int i = tid; i < 384; i += 256) swr2[i] = p.wr2[i];

    // posenc
    if (tid < 128) {
        const int m = tid, pt = blockIdx.x * 128 + m;
#define STP(H, L, STRD, COL, V) do { float _v = (V); u32 _hb = f2h(_v); \
    (H)[m * STRD + (COL)] = (u16)_hb; (L)[m * STRD + (COL)] = (u16)f2h(_v - h2f(_hb)); } while (0)
        for (int d = 0; d < 3; d++) {
            float x = p.pos[pt * 3 + d];
            STP(PHI, PLO, 72, d, x);
            float f = 1.f;
#pragma unroll
            for (int q = 0; q < 10; q++) {
                float s, c; sincosf(x * f, &s, &c);
                STP(PHI, PLO, 72, 3 + 6 * q + d, s);
                STP(PHI, PLO, 72, 3 + 6 * q + 3 + d, c);
                f *= 2.f;
            }
            float y = p.dir[pt * 3 + d];
            STP(DHI, DLO, 40, d, y);
            f = 1.f;
#pragma unroll
            for (int q = 0; q < 4; q++) {
                float s, c; sincosf(y * f, &s, &c);
                STP(DHI, DLO, 40, 3 + 6 * q + d, s);
                STP(DHI, DLO, 40, 3 + 6 * q + 3 + d, c);
                f *= 2.f;
            }
        }
        STP(PHI, PLO, 72, 63, 0.f);
        for (int k = 27; k < 32; k++) STP(DHI, DLO, 40, k, 0.f);
#undef STP
    }
    __syncthreads();

    float acc[4][8][4];
#define ZACC() do { _Pragma("unroll") for (int _a = 0; _a < 4; _a++) \
    _Pragma("unroll") for (int _b = 0; _b < 8; _b++) \
    _Pragma("unroll") for (int _c = 0; _c < 4; _c++) acc[_a][_b][_c] = 0.f; } while (0)
#define LOADBIAS(PTR, N) do { for (int _i = tid; _i < (N); _i += 256) sbias[_i] = (PTR)[_i]; } while (0)
#define ABASE(OFF, STRB) (s2u(sm + (OFF)) + (u32)((wm * 64 + (l & 15)) * (STRB) + ((l >> 4) * 8) * 2))

    // layer 0 (pe -> h)
    ZACC(); LOADBIAS(p.bias[0], 256);
    run_seg<8>(acc, ABASE(O_PEHI, 144), ABASE(O_PELO, 144), 144, 4, 32, g_w + (size_t)SEG_WIN * 64, wn, l);
    __syncthreads();
    epilogue<8>(acc, AHI, ALO, sbias, true, wm, wn, l);
    __syncthreads();

    // hidden layers (NOTE: Wh5/Wh6 live AFTER the H4PE segment — explicit starts)
    for (int i = 0; i < 7; i++) {
        const int seg_start = (i < 5) ? (SEG_H0 + i * 512) : (SEG_H5 + (i - 5) * 512);
        ZACC(); LOADBIAS(p.bias[1 + i], 256);
        run_seg<8>(acc, ABASE(O_AHI, 528), ABASE(O_ALO, 528), 528, 16, 32,
                   g_w + (size_t)seg_start * 64, wn, l);
        if (i == 4)
            run_seg<8>(acc, ABASE(O_PEHI, 144), ABASE(O_PELO, 144), 144, 4, 32,
                       g_w + (size_t)SEG_H4PE * 64, wn, l);
        __syncthreads();
        epilogue<8>(acc, AHI, ALO, sbias, true, wm, wn, l);
        __syncthreads();
    }

    // out layer (features, no relu) + density from h_final (overlapped with MMA)
    ZACC(); LOADBIAS(p.bias[8], 256);
    if (tid < 128) {
        float dsum = p.bout[256];
        for (int k = 0; k < 256; k++)
            dsum += (h2f(AHI[tid * 264 + k]) + h2f(ALO[tid * 264 + k])) * sdcol[k];
        p.out[3 * N_PTS + blockIdx.x * 128 + tid] = fmaxf(dsum, 0.f);
    }
    run_seg<8>(acc, ABASE(O_AHI, 528), ABASE(O_ALO, 528), 528, 16, 32,
               g_w + (size_t)SEG_OUT * 64, wn, l);
    __syncthreads();
    epilogue<8>(acc, AHI, ALO, sbias, false, wm, wn, l);
    __syncthreads();

    // r1: [features, de] @ Wr1, relu, N=128
    ZACC(); LOADBIAS(p.bias[9], 128);
    run_seg<4>(acc, ABASE(O_AHI, 528), ABASE(O_ALO, 528), 528, 16, 16,
               g_w + (size_t)SEG_R1 * 64, wn, l);
    run_seg<4>(acc, ABASE(O_DEHI, 80), ABASE(O_DELO, 80), 80, 2, 16,
               g_w + (size_t)SEG_R1DE * 64, wn, l);
    __syncthreads();
    epilogue<4>(acc, AHI, ALO, sbias, true, wm, wn, l);
    __syncthreads();

    // r2 + sigmoid
    if (tid < 128) {
        const int pt = blockIdx.x * 128 + tid;
        float r0 = 0.f, r1 = 0.f, r2 = 0.f;
        for (int k = 0; k < 128; k++) {
            float hv = h2f(AHI[tid * 264 + k]) + h2f(ALO[tid * 264 + k]);
            r0 += hv * swr2[k * 3 + 0];
            r1 += hv * swr2[k * 3 + 1];
            r2 += hv * swr2[k * 3 + 2];
        }
        p.out[pt * 3 + 0] = 1.f / (1.f + expf(-(r0 + p.br2[0])));
        p.out[pt * 3 + 1] = 1.f / (1.f + expf(-(r1 + p.br2[1])));
        p.out[pt * 3 + 2] = 1.f / (1.f + expf(-(r2 + p.br2[2])));
    }
}

// ---------- host ----------
extern "C" void kernel_launch(void* const* d_in, const int* in_sizes, int n_in,
                              void* d_out, int out_size)
{
    const float* pos  = (const float*)d_in[0];
    const float* dir  = (const float*)d_in[1];
    const float* Win  = (const float*)d_in[2];
    const float* bin  = (const float*)d_in[3];
    const float* Wh[7]; const float* bh[7];
    for (int i = 0; i < 7; i++) { Wh[i] = (const float*)d_in[4 + 2 * i]; bh[i] = (const float*)d_in[5 + 2 * i]; }
    const float* Wout = (const float*)d_in[18];
    const float* bout = (const float*)d_in[19];
    const float* Wr1  = (const float*)d_in[20];
    const float* br1  = (const float*)d_in[21];
    const float* Wr2  = (const float*)d_in[22];
    const float* br2  = (const float*)d_in[23];

    static PrepP pp;
    pp.seg[0]  = { Win,               256, 63,  256, 32, SEG_WIN };
    for (int i = 0; i < 5; i++)
        pp.seg[1 + i] = { Wh[i],      256, 256, 256, 32, SEG_H0 + i * 512 };
    pp.seg[6]  = { Wh[4] + 256 * 256, 256, 63,  256, 32, SEG_H4PE };
    pp.seg[7]  = { Wh[5],             256, 256, 256, 32, SEG_H5 };
    pp.seg[8]  = { Wh[6],             256, 256, 256, 32, SEG_H6 };
    pp.seg[9]  = { Wout,              257, 256, 256, 32, SEG_OUT };
    pp.seg[10] = { Wr1,               128, 256, 128, 16, SEG_R1 };
    pp.seg[11] = { Wr1 + 256 * 128,   128, 27,  128, 16, SEG_R1DE };
    pp.Wout = Wout;

    static Params p;
    p.pos = pos; p.dir = dir; p.bout = bout; p.wr2 = Wr2; p.br2 = br2;
    p.bias[0] = bin;
    for (int i = 0; i < 7; i++) p.bias[1 + i] = bh[i];
    p.bias[8] = bout; p.bias[9] = br1;
    p.out = (float*)d_out;

    prep_kernel<<<TOTB / 8, 256>>>(pp);
    cudaFuncSetAttribute(nerf_mma, cudaFuncAttributeMaxDynamicSharedMemorySize, SMEM_TOTAL);
    nerf_mma<<<N_PTS / 128, 256, SMEM_TOTAL>>>(p);
}

// round 8
// speedup vs baseline: 6.8470x; 2.3417x over previous
#include <cuda_runtime.h>
#include <cuda_fp16.h>
#include <stdint.h>
#include <math.h>

typedef uint32_t u32; typedef uint64_t u64; typedef unsigned short u16;

#define N_PTS 262144
#define TOTB 4640

// weight blocks in B-fragment order (fp16 hi only): block b = 256B: lane l at [b*32+l]
__device__ __align__(16) u64 g_w[TOTB * 32];
__device__ float g_dcol[256];

// seg block offsets (layout: Win | Wh0..Wh4 | H4PE | Wh5 | Wh6 | Wout | Wr1 | Wr1de)
#define SEG_WIN  0
#define SEG_H0   128
#define SEG_H4PE 2688
#define SEG_H5   2816
#define SEG_H6   3328
#define SEG_OUT  3840
#define SEG_R1   4352
#define SEG_R1DE 4608

// ---------- fp16 helpers (RNE) ----------
__device__ __forceinline__ u32 f2h(float f) {
    return (u32)__half_as_ushort(__float2half_rn(f));
}
__device__ __forceinline__ float h2f(u32 h) {
    return __half2float(__ushort_as_half((u16)h));
}

__device__ __forceinline__ u32 s2u(const void* p) {
    u32 a;
    asm("{ .reg .u64 t; cvta.to.shared.u64 t, %1; cvt.u32.u64 %0, t; }" : "=r"(a) : "l"(p));
    return a;
}

#define LDMX4(R, addr) \
    asm volatile("ldmatrix.sync.aligned.m8n8.x4.shared.b16 {%0,%1,%2,%3}, [%4];" \
        : "=r"((R)[0]), "=r"((R)[1]), "=r"((R)[2]), "=r"((R)[3]) : "r"(addr))

#define MMA(D, A, b0, b1) \
    asm volatile("mma.sync.aligned.m16n8k16.row.col.f32.f16.f16.f32 " \
        "{%0,%1,%2,%3},{%4,%5,%6,%7},{%8,%9},{%0,%1,%2,%3};" \
        : "+f"((D)[0]), "+f"((D)[1]), "+f"((D)[2]), "+f"((D)[3]) \
        : "r"((A)[0]), "r"((A)[1]), "r"((A)[2]), "r"((A)[3]), "r"(b0), "r"(b1))

// ---------- SMEM layout (bytes) ----------
#define O_AHI  0
#define O_PEHI 67584
#define O_DEHI 86016
#define O_BIAS 96256
#define O_DCOL 97280
#define O_WR2  98304
#define SMEM_TOTAL 99840

// ---------- prep kernel: weights -> fragment order, fp16 ----------
struct Seg { const float* src; int rs, kv, nv, NT, start; };
struct PrepP { Seg seg[12]; const float* Wout; };

__global__ void prep_kernel(PrepP pp) {
    int b = blockIdx.x * 8 + (threadIdx.x >> 5);
    int l = threadIdx.x & 31;
    if (blockIdx.x == 0) g_dcol[threadIdx.x] = pp.Wout[threadIdx.x * 257 + 256];
    int si = 0;
#pragma unroll
    for (int i = 1; i < 12; i++) if (b >= pp.seg[i].start) si = i;
    Seg sg = pp.seg[si];
    int rel = b - sg.start;
    int s = rel / sg.NT, tg = rel % sg.NT;
    int n = tg * 8 + (l >> 2);
    u64 hv = 0;
#pragma unroll
    for (int idx = 0; idx < 4; idx++) {
        int r = idx >> 1, j = idx & 1;
        int k = s * 16 + (l & 3) * 2 + r * 8 + j;
        float w = (k < sg.kv && n < sg.nv) ? sg.src[(size_t)k * sg.rs + n] : 0.f;
        hv |= (u64)f2h(w) << (16 * idx);
    }
    g_w[(size_t)b * 32 + l] = hv;
}

// ---------- main kernel ----------
struct Params {
    const float *pos, *dir, *bout, *wr2, *br2;
    const float* bias[10];
    float* out;
};

// MMA over one K-segment. a_base: smem addr incl. this thread's row/koff.
template<int NTW>
__device__ __forceinline__ void run_seg(float (&acc)[4][8][4], u32 a_base,
    int strideB, int S, int NT, const u64* __restrict__ wseg, int wn, int l)
{
    for (int s = 0; s < S; s++) {
        u32 ah[4][4];
#pragma unroll
        for (int mt = 0; mt < 4; mt++)
            LDMX4(ah[mt], a_base + mt * 16 * strideB + s * 32);
        const u64* blk = wseg + (size_t)(s * NT + wn * NTW) * 32 + l;
        u64 wh[NTW];
#pragma unroll
        for (int t = 0; t < NTW; t++) wh[t] = blk[t * 32];
#pragma unroll
        for (int t = 0; t < NTW; t++) {
            u32 h0 = (u32)wh[t], h1 = (u32)(wh[t] >> 32);
#pragma unroll
            for (int mt = 0; mt < 4; mt++) MMA(acc[mt][t], ah[mt], h0, h1);
        }
    }
}

template<int NTW>
__device__ __forceinline__ void epilogue(float (&acc)[4][8][4], u16* HI,
    const float* sbias, bool relu, int wm, int wn, int l)
{
    int cb = wn * NTW * 8 + (l & 3) * 2;
    int rb = wm * 64 + (l >> 2);
#pragma unroll
    for (int mt = 0; mt < 4; mt++)
#pragma unroll
        for (int t = 0; t < NTW; t++)
#pragma unroll
            for (int h = 0; h < 2; h++) {
                int r = rb + mt * 16 + h * 8, c = cb + t * 8;
                float v0 = acc[mt][t][2 * h]     + sbias[c];
                float v1 = acc[mt][t][2 * h + 1] + sbias[c + 1];
                if (relu) { v0 = fmaxf(v0, 0.f); v1 = fmaxf(v1, 0.f); }
                *(u32*)&HI[r * 264 + c] = f2h(v0) | (f2h(v1) << 16);
            }
}

__global__ void __launch_bounds__(256, 1) nerf_mma(Params p)
{
    extern __shared__ char sm[];
    u16* AHI = (u16*)(sm + O_AHI);
    u16* PHI = (u16*)(sm + O_PEHI);
    u16* DHI = (u16*)(sm + O_DEHI);
    float* sbias = (float*)(sm + O_BIAS);
    float* sdcol = (float*)(sm + O_DCOL);
    float* swr2  = (float*)(sm + O_WR2);

    const int tid = threadIdx.x;
    const int l = tid & 31, wid = tid >> 5;
    const int wm = wid >> 2, wn = wid & 3;

    sdcol[tid] = g_dcol[tid];
    for (int i = tid; i < 384; i += 256) swr2[i] = p.wr2[i];

    // posenc
    if (tid < 128) {
        const int m = tid, pt = blockIdx.x * 128 + m;
#define STP(H, STRD, COL, V) (H)[m * STRD + (COL)] = (u16)f2h(V)
        for (int d = 0; d < 3; d++) {
            float x = p.pos[pt * 3 + d];
            STP(PHI, 72, d, x);
            float f = 1.f;
#pragma unroll
            for (int q = 0; q < 10; q++) {
                float s, c; sincosf(x * f, &s, &c);
                STP(PHI, 72, 3 + 6 * q + d, s);
                STP(PHI, 72, 3 + 6 * q + 3 + d, c);
                f *= 2.f;
            }
            float y = p.dir[pt * 3 + d];
            STP(DHI, 40, d, y);
            f = 1.f;
#pragma unroll
            for (int q = 0; q < 4; q++) {
                float s, c; sincosf(y * f, &s, &c);
                STP(DHI, 40, 3 + 6 * q + d, s);
                STP(DHI, 40, 3 + 6 * q + 3 + d, c);
                f *= 2.f;
            }
        }
        STP(PHI, 72, 63, 0.f);
        for (int k = 27; k < 32; k++) STP(DHI, 40, k, 0.f);
#undef STP
    }
    __syncthreads();

    float acc[4][8][4];
#define ZACC() do { _Pragma("unroll") for (int _a = 0; _a < 4; _a++) \
    _Pragma("unroll") for (int _b = 0; _b < 8; _b++) \
    _Pragma("unroll") for (int _c = 0; _c < 4; _c++) acc[_a][_b][_c] = 0.f; } while (0)
#define LOADBIAS(PTR, N) do { for (int _i = tid; _i < (N); _i += 256) sbias[_i] = (PTR)[_i]; } while (0)
#define ABASE(OFF, STRB) (s2u(sm + (OFF)) + (u32)((wm * 64 + (l & 15)) * (STRB) + ((l >> 4) * 8) * 2))

    // layer 0 (pe -> h)
    ZACC(); LOADBIAS(p.bias[0], 256);
    run_seg<8>(acc, ABASE(O_PEHI, 144), 144, 4, 32, g_w + (size_t)SEG_WIN * 32, wn, l);
    __syncthreads();
    epilogue<8>(acc, AHI, sbias, true, wm, wn, l);
    __syncthreads();

    // hidden layers (NOTE: Wh5/Wh6 live AFTER the H4PE segment — explicit starts)
    for (int i = 0; i < 7; i++) {
        const int seg_start = (i < 5) ? (SEG_H0 + i * 512) : (SEG_H5 + (i - 5) * 512);
        ZACC(); LOADBIAS(p.bias[1 + i], 256);
        run_seg<8>(acc, ABASE(O_AHI, 528), 528, 16, 32,
                   g_w + (size_t)seg_start * 32, wn, l);
        if (i == 4)
            run_seg<8>(acc, ABASE(O_PEHI, 144), 144, 4, 32,
                       g_w + (size_t)SEG_H4PE * 32, wn, l);
        __syncthreads();
        epilogue<8>(acc, AHI, sbias, true, wm, wn, l);
        __syncthreads();
    }

    // out layer (features, no relu) + density from h_final (overlapped with MMA)
    ZACC(); LOADBIAS(p.bias[8], 256);
    if (tid < 128) {
        float dsum = p.bout[256];
        for (int k = 0; k < 256; k++)
            dsum += h2f(AHI[tid * 264 + k]) * sdcol[k];
        p.out[3 * N_PTS + blockIdx.x * 128 + tid] = fmaxf(dsum, 0.f);
    }
    run_seg<8>(acc, ABASE(O_AHI, 528), 528, 16, 32,
               g_w + (size_t)SEG_OUT * 32, wn, l);
    __syncthreads();
    epilogue<8>(acc, AHI, sbias, false, wm, wn, l);
    __syncthreads();

    // r1: [features, de] @ Wr1, relu, N=128
    ZACC(); LOADBIAS(p.bias[9], 128);
    run_seg<4>(acc, ABASE(O_AHI, 528), 528, 16, 16,
               g_w + (size_t)SEG_R1 * 32, wn, l);
    run_seg<4>(acc, ABASE(O_DEHI, 80), 80, 2, 16,
               g_w + (size_t)SEG_R1DE * 32, wn, l);
    __syncthreads();
    epilogue<4>(acc, AHI, sbias, true, wm, wn, l);
    __syncthreads();

    // r2 + sigmoid
    if (tid < 128) {
        const int pt = blockIdx.x * 128 + tid;
        float r0 = 0.f, r1 = 0.f, r2 = 0.f;
        for (int k = 0; k < 128; k++) {
            float hv = h2f(AHI[tid * 264 + k]);
            r0 += hv * swr2[k * 3 + 0];
            r1 += hv * swr2[k * 3 + 1];
            r2 += hv * swr2[k * 3 + 2];
        }
        p.out[pt * 3 + 0] = 1.f / (1.f + expf(-(r0 + p.br2[0])));
        p.out[pt * 3 + 1] = 1.f / (1.f + expf(-(r1 + p.br2[1])));
        p.out[pt * 3 + 2] = 1.f / (1.f + expf(-(r2 + p.br2[2])));
    }
}

// ---------- host ----------
extern "C" void kernel_launch(void* const* d_in, const int* in_sizes, int n_in,
                              void* d_out, int out_size)
{
    const float* pos  = (const float*)d_in[0];
    const float* dir  = (const float*)d_in[1];
    const float* Win  = (const float*)d_in[2];
    const float* bin  = (const float*)d_in[3];
    const float* Wh[7]; const float* bh[7];
    for (int i = 0; i < 7; i++) { Wh[i] = (const float*)d_in[4 + 2 * i]; bh[i] = (const float*)d_in[5 + 2 * i]; }
    const float* Wout = (const float*)d_in[18];
    const float* bout = (const float*)d_in[19];
    const float* Wr1  = (const float*)d_in[20];
    const float* br1  = (const float*)d_in[21];
    const float* Wr2  = (const float*)d_in[22];
    const float* br2  = (const float*)d_in[23];

    static PrepP pp;
    pp.seg[0]  = { Win,               256, 63,  256, 32, SEG_WIN };
    for (int i = 0; i < 5; i++)
        pp.seg[1 + i] = { Wh[i],      256, 256, 256, 32, SEG_H0 + i * 512 };
    pp.seg[6]  = { Wh[4] + 256 * 256, 256, 63,  256, 32, SEG_H4PE };
    pp.seg[7]  = { Wh[5],             256, 256, 256, 32, SEG_H5 };
    pp.seg[8]  = { Wh[6],             256, 256, 256, 32, SEG_H6 };
    pp.seg[9]  = { Wout,              257, 256, 256, 32, SEG_OUT };
    pp.seg[10] = { Wr1,               128, 256, 128, 16, SEG_R1 };
    pp.seg[11] = { Wr1 + 256 * 128,   128, 27,  128, 16, SEG_R1DE };
    pp.Wout = Wout;

    static Params p;
    p.pos = pos; p.dir = dir; p.bout = bout; p.wr2 = Wr2; p.br2 = br2;
    p.bias[0] = bin;
    for (int i = 0; i < 7; i++) p.bias[1 + i] = bh[i];
    p.bias[8] = bout; p.bias[9] = br1;
    p.out = (float*)d_out;

    prep_kernel<<<TOTB / 8, 256>>>(pp);
    cudaFuncSetAttribute(nerf_mma, cudaFuncAttributeMaxDynamicSharedMemorySize, SMEM_TOTAL);
    nerf_mma<<<N_PTS / 128, 256, SMEM_TOTAL>>>(p);
}

// round 9
// speedup vs baseline: 6.9454x; 1.0144x over previous
#include <cuda_runtime.h>
#include <cuda_fp16.h>
#include <stdint.h>
#include <math.h>

typedef uint32_t u32; typedef uint64_t u64; typedef unsigned short u16;

#define N_PTS 262144
#define TOTB 4640

// weight blocks in B-fragment order (fp16): block b = 256B: lane l at [b*32+l]
__device__ __align__(16) u64 g_w[TOTB * 32];
__device__ float g_dcol[256];

// seg block offsets (layout: Win | Wh0..Wh4 | H4PE | Wh5 | Wh6 | Wout | Wr1 | Wr1de)
#define SEG_WIN  0
#define SEG_H0   128
#define SEG_H4PE 2688
#define SEG_H5   2816
#define SEG_H6   3328
#define SEG_OUT  3840
#define SEG_R1   4352
#define SEG_R1DE 4608

// ---------- fp16 helpers (RNE) ----------
__device__ __forceinline__ u32 f2h(float f) {
    return (u32)__half_as_ushort(__float2half_rn(f));
}
__device__ __forceinline__ float h2f(u32 h) {
    return __half2float(__ushort_as_half((u16)h));
}

__device__ __forceinline__ u32 s2u(const void* p) {
    u32 a;
    asm("{ .reg .u64 t; cvta.to.shared.u64 t, %1; cvt.u32.u64 %0, t; }" : "=r"(a) : "l"(p));
    return a;
}

#define LDMX4(R, addr) \
    asm volatile("ldmatrix.sync.aligned.m8n8.x4.shared.b16 {%0,%1,%2,%3}, [%4];" \
        : "=r"((R)[0]), "=r"((R)[1]), "=r"((R)[2]), "=r"((R)[3]) : "r"(addr))

#define MMA(D, A, b0, b1) \
    asm volatile("mma.sync.aligned.m16n8k16.row.col.f32.f16.f16.f32 " \
        "{%0,%1,%2,%3},{%4,%5,%6,%7},{%8,%9},{%0,%1,%2,%3};" \
        : "+f"((D)[0]), "+f"((D)[1]), "+f"((D)[2]), "+f"((D)[3]) \
        : "r"((A)[0]), "r"((A)[1]), "r"((A)[2]), "r"((A)[3]), "r"(b0), "r"(b1))

// ---------- SMEM layout (bytes) ----------
#define O_AHI  0
#define O_PEHI 67584
#define O_DEHI 86016
#define O_BIAS 96256
#define O_DCOL 97280
#define O_WR2  98304
#define SMEM_TOTAL 99840

// ---------- prep kernel: weights -> fragment order, fp16 ----------
struct Seg { const float* src; int rs, kv, nv, NT, start; };
struct PrepP { Seg seg[12]; const float* Wout; };

__global__ void prep_kernel(PrepP pp) {
    int b = blockIdx.x * 8 + (threadIdx.x >> 5);
    int l = threadIdx.x & 31;
    if (blockIdx.x == 0) g_dcol[threadIdx.x] = pp.Wout[threadIdx.x * 257 + 256];
    int si = 0;
#pragma unroll
    for (int i = 1; i < 12; i++) if (b >= pp.seg[i].start) si = i;
    Seg sg = pp.seg[si];
    int rel = b - sg.start;
    int s = rel / sg.NT, tg = rel % sg.NT;
    int n = tg * 8 + (l >> 2);
    u64 hv = 0;
#pragma unroll
    for (int idx = 0; idx < 4; idx++) {
        int r = idx >> 1, j = idx & 1;
        int k = s * 16 + (l & 3) * 2 + r * 8 + j;
        float w = (k < sg.kv && n < sg.nv) ? sg.src[(size_t)k * sg.rs + n] : 0.f;
        hv |= (u64)f2h(w) << (16 * idx);
    }
    g_w[(size_t)b * 32 + l] = hv;
}

// ---------- main kernel ----------
struct Params {
    const float *pos, *dir, *bout, *wr2, *br2;
    const float* bias[10];
    float* out;
};

// MMA over one K-segment with one-step weight prefetch pipeline.
template<int NTW>
__device__ __forceinline__ void run_seg(float (&acc)[4][8][4], u32 a_base,
    int strideB, int S, int NT, const u64* __restrict__ wseg, int wn, int l)
{
    const u64* base = wseg + (size_t)(wn * NTW) * 32 + l;
    u64 wh[NTW];
#pragma unroll
    for (int t = 0; t < NTW; t++) wh[t] = base[t * 32];
    for (int s = 0; s < S; s++) {
        u32 ah[4][4];
#pragma unroll
        for (int mt = 0; mt < 4; mt++)
            LDMX4(ah[mt], a_base + mt * 16 * strideB + s * 32);
        u64 wnx[NTW];
        if (s + 1 < S) {
            const u64* nb = base + (size_t)(s + 1) * NT * 32;
#pragma unroll
            for (int t = 0; t < NTW; t++) wnx[t] = nb[t * 32];
        }
#pragma unroll
        for (int t = 0; t < NTW; t++) {
            u32 h0 = (u32)wh[t], h1 = (u32)(wh[t] >> 32);
#pragma unroll
            for (int mt = 0; mt < 4; mt++) MMA(acc[mt][t], ah[mt], h0, h1);
        }
        if (s + 1 < S) {
#pragma unroll
            for (int t = 0; t < NTW; t++) wh[t] = wnx[t];
        }
    }
}

template<int NTW>
__device__ __forceinline__ void epilogue(float (&acc)[4][8][4], u16* HI,
    const float* sbias, bool relu, int wm, int wn, int l)
{
    int cb = wn * NTW * 8 + (l & 3) * 2;
    int rb = wm * 64 + (l >> 2);
#pragma unroll
    for (int mt = 0; mt < 4; mt++)
#pragma unroll
        for (int t = 0; t < NTW; t++)
#pragma unroll
            for (int h = 0; h < 2; h++) {
                int r = rb + mt * 16 + h * 8, c = cb + t * 8;
                float v0 = acc[mt][t][2 * h]     + sbias[c];
                float v1 = acc[mt][t][2 * h + 1] + sbias[c + 1];
                if (relu) { v0 = fmaxf(v0, 0.f); v1 = fmaxf(v1, 0.f); }
                *(u32*)&HI[r * 264 + c] = f2h(v0) | (f2h(v1) << 16);
            }
}

__global__ void __launch_bounds__(256, 1) nerf_mma(Params p)
{
    extern __shared__ char sm[];
    u16* AHI = (u16*)(sm + O_AHI);
    u16* PHI = (u16*)(sm + O_PEHI);
    u16* DHI = (u16*)(sm + O_DEHI);
    float* sbias = (float*)(sm + O_BIAS);
    float* sdcol = (float*)(sm + O_DCOL);
    float* swr2  = (float*)(sm + O_WR2);
    float* sred  = (float*)(sm + O_PEHI);   // scratch (PE dead after layer 4)

    const int tid = threadIdx.x;
    const int l = tid & 31, wid = tid >> 5;
    const int wm = wid >> 2, wn = wid & 3;

    sdcol[tid] = g_dcol[tid];
    for (int i = tid; i < 384; i += 256) swr2[i] = p.wr2[i];

    // posenc
    if (tid < 128) {
        const int m = tid, pt = blockIdx.x * 128 + m;
#define STP(H, STRD, COL, V) (H)[m * STRD + (COL)] = (u16)f2h(V)
        for (int d = 0; d < 3; d++) {
            float x = p.pos[pt * 3 + d];
            STP(PHI, 72, d, x);
            float f = 1.f;
#pragma unroll
            for (int q = 0; q < 10; q++) {
                float s, c; sincosf(x * f, &s, &c);
                STP(PHI, 72, 3 + 6 * q + d, s);
                STP(PHI, 72, 3 + 6 * q + 3 + d, c);
                f *= 2.f;
            }
            float y = p.dir[pt * 3 + d];
            STP(DHI, 40, d, y);
            f = 1.f;
#pragma unroll
            for (int q = 0; q < 4; q++) {
                float s, c; sincosf(y * f, &s, &c);
                STP(DHI, 40, 3 + 6 * q + d, s);
                STP(DHI, 40, 3 + 6 * q + 3 + d, c);
                f *= 2.f;
            }
        }
        STP(PHI, 72, 63, 0.f);
        for (int k = 27; k < 32; k++) STP(DHI, 40, k, 0.f);
#undef STP
    }
    __syncthreads();

    float acc[4][8][4];
#define ZACC() do { _Pragma("unroll") for (int _a = 0; _a < 4; _a++) \
    _Pragma("unroll") for (int _b = 0; _b < 8; _b++) \
    _Pragma("unroll") for (int _c = 0; _c < 4; _c++) acc[_a][_b][_c] = 0.f; } while (0)
#define LOADBIAS(PTR, N) do { for (int _i = tid; _i < (N); _i += 256) sbias[_i] = (PTR)[_i]; } while (0)
#define ABASE(OFF, STRB) (s2u(sm + (OFF)) + (u32)((wm * 64 + (l & 15)) * (STRB) + ((l >> 4) * 8) * 2))

    // layer 0 (pe -> h)
    ZACC(); LOADBIAS(p.bias[0], 256);
    run_seg<8>(acc, ABASE(O_PEHI, 144), 144, 4, 32, g_w + (size_t)SEG_WIN * 32, wn, l);
    __syncthreads();
    epilogue<8>(acc, AHI, sbias, true, wm, wn, l);
    __syncthreads();

    // hidden layers (Wh5/Wh6 live AFTER the H4PE segment — explicit starts)
    for (int i = 0; i < 7; i++) {
        const int seg_start = (i < 5) ? (SEG_H0 + i * 512) : (SEG_H5 + (i - 5) * 512);
        ZACC(); LOADBIAS(p.bias[1 + i], 256);
        run_seg<8>(acc, ABASE(O_AHI, 528), 528, 16, 32,
                   g_w + (size_t)seg_start * 32, wn, l);
        if (i == 4)
            run_seg<8>(acc, ABASE(O_PEHI, 144), 144, 4, 32,
                       g_w + (size_t)SEG_H4PE * 32, wn, l);
        __syncthreads();
        epilogue<8>(acc, AHI, sbias, true, wm, wn, l);
        __syncthreads();
    }

    // out layer: density partials (all 256 threads, u64 LDS) + features MMA
    ZACC(); LOADBIAS(p.bias[8], 256);
    {
        const int m = tid & 127, half = tid >> 7;
        float dsum = 0.f;
        const u64* arow = (const u64*)(AHI + m * 264 + half * 128);
        const float* dc = sdcol + half * 128;
#pragma unroll 8
        for (int kb = 0; kb < 32; kb++) {
            u64 v = arow[kb];
            dsum += h2f((u32)(v      ) & 0xFFFF) * dc[kb * 4 + 0];
            dsum += h2f((u32)(v >> 16) & 0xFFFF) * dc[kb * 4 + 1];
            dsum += h2f((u32)(v >> 32) & 0xFFFF) * dc[kb * 4 + 2];
            dsum += h2f((u32)(v >> 48)         ) * dc[kb * 4 + 3];
        }
        sred[tid] = dsum;
    }
    run_seg<8>(acc, ABASE(O_AHI, 528), 528, 16, 32,
               g_w + (size_t)SEG_OUT * 32, wn, l);
    __syncthreads();
    if (tid < 128)
        p.out[3 * N_PTS + blockIdx.x * 128 + tid] =
            fmaxf(sred[tid] + sred[tid + 128] + p.bout[256], 0.f);
    epilogue<8>(acc, AHI, sbias, false, wm, wn, l);
    __syncthreads();

    // r1: [features, de] @ Wr1, relu, N=128
    ZACC(); LOADBIAS(p.bias[9], 128);
    run_seg<4>(acc, ABASE(O_AHI, 528), 528, 16, 16,
               g_w + (size_t)SEG_R1 * 32, wn, l);
    run_seg<4>(acc, ABASE(O_DEHI, 80), 80, 2, 16,
               g_w + (size_t)SEG_R1DE * 32, wn, l);
    __syncthreads();
    epilogue<4>(acc, AHI, sbias, true, wm, wn, l);
    __syncthreads();

    // r2 + sigmoid: partials over half the k-range per thread, SMEM reduce
    {
        const int m = tid & 127, half = tid >> 7;
        float r0 = 0.f, r1 = 0.f, r2 = 0.f;
        const u64* arow = (const u64*)(AHI + m * 264 + half * 64);
#pragma unroll 4
        for (int kb = 0; kb < 16; kb++) {
            u64 v = arow[kb];
#pragma unroll
            for (int j = 0; j < 4; j++) {
                float hv = h2f((u32)(v >> (16 * j)) & 0xFFFF);
                const float* w = swr2 + (half * 64 + kb * 4 + j) * 3;
                r0 += hv * w[0]; r1 += hv * w[1]; r2 += hv * w[2];
            }
        }
        sred[tid] = r0; sred[256 + tid] = r1; sred[512 + tid] = r2;
    }
    __syncthreads();
    if (tid < 128) {
        const int pt = blockIdx.x * 128 + tid;
        float r0 = sred[tid] + sred[tid + 128] + p.br2[0];
        float r1 = sred[256 + tid] + sred[384 + tid] + p.br2[1];
        float r2 = sred[512 + tid] + sred[640 + tid] + p.br2[2];
        p.out[pt * 3 + 0] = 1.f / (1.f + expf(-r0));
        p.out[pt * 3 + 1] = 1.f / (1.f + expf(-r1));
        p.out[pt * 3 + 2] = 1.f / (1.f + expf(-r2));
    }
}

// ---------- host ----------
extern "C" void kernel_launch(void* const* d_in, const int* in_sizes, int n_in,
                              void* d_out, int out_size)
{
    const float* pos  = (const float*)d_in[0];
    const float* dir  = (const float*)d_in[1];
    const float* Win  = (const float*)d_in[2];
    const float* bin  = (const float*)d_in[3];
    const float* Wh[7]; const float* bh[7];
    for (int i = 0; i < 7; i++) { Wh[i] = (const float*)d_in[4 + 2 * i]; bh[i] = (const float*)d_in[5 + 2 * i]; }
    const float* Wout = (const float*)d_in[18];
    const float* bout = (const float*)d_in[19];
    const float* Wr1  = (const float*)d_in[20];
    const float* br1  = (const float*)d_in[21];
    const float* Wr2  = (const float*)d_in[22];
    const float* br2  = (const float*)d_in[23];

    static PrepP pp;
    pp.seg[0]  = { Win,               256, 63,  256, 32, SEG_WIN };
    for (int i = 0; i < 5; i++)
        pp.seg[1 + i] = { Wh[i],      256, 256, 256, 32, SEG_H0 + i * 512 };
    pp.seg[6]  = { Wh[4] + 256 * 256, 256, 63,  256, 32, SEG_H4PE };
    pp.seg[7]  = { Wh[5],             256, 256, 256, 32, SEG_H5 };
    pp.seg[8]  = { Wh[6],             256, 256, 256, 32, SEG_H6 };
    pp.seg[9]  = { Wout,              257, 256, 256, 32, SEG_OUT };
    pp.seg[10] = { Wr1,               128, 256, 128, 16, SEG_R1 };
    pp.seg[11] = { Wr1 + 256 * 128,   128, 27,  128, 16, SEG_R1DE };
    pp.Wout = Wout;

    static Params p;
    p.pos = pos; p.dir = dir; p.bout = bout; p.wr2 = Wr2; p.br2 = br2;
    p.bias[0] = bin;
    for (int i = 0; i < 7; i++) p.bias[1 + i] = bh[i];
    p.bias[8] = bout; p.bias[9] = br1;
    p.out = (float*)d_out;

    prep_kernel<<<TOTB / 8, 256>>>(pp);
    cudaFuncSetAttribute(nerf_mma, cudaFuncAttributeMaxDynamicSharedMemorySize, SMEM_TOTAL);
    nerf_mma<<<N_PTS / 128, 256, SMEM_TOTAL>>>(p);
}

// round 10
// speedup vs baseline: 8.4047x; 1.2101x over previous
#include <cuda_runtime.h>
#include <cuda_fp16.h>
#include <stdint.h>
#include <math.h>

typedef uint32_t u32; typedef uint64_t u64; typedef unsigned short u16;

#define N_PTS 262144
#define TOTB 4640

// weight blocks in B-fragment order (fp16): block b = 256B: lane l at [b*32+l]
__device__ __align__(16) u64 g_w[TOTB * 32];
__device__ float g_dcol[256];

// seg block offsets (layout: Win | Wh0..Wh4 | H4PE | Wh5 | Wh6 | Wout | Wr1 | Wr1de)
#define SEG_WIN  0
#define SEG_H0   128
#define SEG_H4PE 2688
#define SEG_H5   2816
#define SEG_H6   3328
#define SEG_OUT  3840
#define SEG_R1   4352
#define SEG_R1DE 4608

// ---------- fp16 helpers ----------
__device__ __forceinline__ u32 f2h(float f) {
    return (u32)__half_as_ushort(__float2half_rn(f));
}
__device__ __forceinline__ float h2f(u32 h) {
    return __half2float(__ushort_as_half((u16)h));
}

__device__ __forceinline__ u32 s2u(const void* p) {
    u32 a;
    asm("{ .reg .u64 t; cvta.to.shared.u64 t, %1; cvt.u32.u64 %0, t; }" : "=r"(a) : "l"(p));
    return a;
}

#define LDMX4(R, addr) \
    asm volatile("ldmatrix.sync.aligned.m8n8.x4.shared.b16 {%0,%1,%2,%3}, [%4];" \
        : "=r"((R)[0]), "=r"((R)[1]), "=r"((R)[2]), "=r"((R)[3]) : "r"(addr))

#define MMA(D, A, b0, b1) \
    asm volatile("mma.sync.aligned.m16n8k16.row.col.f32.f16.f16.f32 " \
        "{%0,%1,%2,%3},{%4,%5,%6,%7},{%8,%9},{%0,%1,%2,%3};" \
        : "+f"((D)[0]), "+f"((D)[1]), "+f"((D)[2]), "+f"((D)[3]) \
        : "r"((A)[0]), "r"((A)[1]), "r"((A)[2]), "r"((A)[3]), "r"(b0), "r"(b1))

// ---------- SMEM layout (bytes), M=64 tile ----------
#define O_A0   0
#define O_A1   33792
#define O_PEHI 67584
#define O_DEHI 76800
#define O_BIAS 81920
#define O_DCOL 91648
#define O_WR2  92672
#define SMEM_TOTAL 94208

// ---------- prep kernel: weights -> fragment order, fp16 (unchanged) ----------
struct Seg { const float* src; int rs, kv, nv, NT, start; };
struct PrepP { Seg seg[12]; const float* Wout; };

__global__ void prep_kernel(PrepP pp) {
    int b = blockIdx.x * 8 + (threadIdx.x >> 5);
    int l = threadIdx.x & 31;
    if (blockIdx.x == 0) g_dcol[threadIdx.x] = pp.Wout[threadIdx.x * 257 + 256];
    int si = 0;
#pragma unroll
    for (int i = 1; i < 12; i++) if (b >= pp.seg[i].start) si = i;
    Seg sg = pp.seg[si];
    int rel = b - sg.start;
    int s = rel / sg.NT, tg = rel % sg.NT;
    int n = tg * 8 + (l >> 2);
    u64 hv = 0;
#pragma unroll
    for (int idx = 0; idx < 4; idx++) {
        int r = idx >> 1, j = idx & 1;
        int k = s * 16 + (l & 3) * 2 + r * 8 + j;
        float w = (k < sg.kv && n < sg.nv) ? sg.src[(size_t)k * sg.rs + n] : 0.f;
        hv |= (u64)f2h(w) << (16 * idx);
    }
    g_w[(size_t)b * 32 + l] = hv;
}

// ---------- main kernel ----------
struct Params {
    const float *pos, *dir, *bout, *wr2, *br2;
    const float* bias[10];
    float* out;
};

// MMA over one K-segment, M=64 (2 m-tiles per warp).
template<int NTW>
__device__ __forceinline__ void run_seg(float (&acc)[2][NTW][4], u32 a_base,
    int strideB, int S, int NT, const u64* __restrict__ wseg, int wn, int l)
{
    for (int s = 0; s < S; s++) {
        u32 ah[2][4];
        LDMX4(ah[0], a_base + s * 32);
        LDMX4(ah[1], a_base + 16 * strideB + s * 32);
        const u64* blk = wseg + (size_t)(s * NT + wn * NTW) * 32 + l;
        u64 wh[NTW];
#pragma unroll
        for (int t = 0; t < NTW; t++) wh[t] = blk[t * 32];
#pragma unroll
        for (int t = 0; t < NTW; t++) {
            u32 h0 = (u32)wh[t], h1 = (u32)(wh[t] >> 32);
            MMA(acc[0][t], ah[0], h0, h1);
            MMA(acc[1][t], ah[1], h0, h1);
        }
    }
}

template<int NTW>
__device__ __forceinline__ void epilogue(float (&acc)[2][NTW][4], u16* HI,
    const float* sbias, bool relu, int wm, int wn, int l)
{
    int cb = wn * NTW * 8 + (l & 3) * 2;
    int rb = wm * 32 + (l >> 2);
#pragma unroll
    for (int mt = 0; mt < 2; mt++)
#pragma unroll
        for (int t = 0; t < NTW; t++)
#pragma unroll
            for (int h = 0; h < 2; h++) {
                int r = rb + mt * 16 + h * 8, c = cb + t * 8;
                float v0 = acc[mt][t][2 * h]     + sbias[c];
                float v1 = acc[mt][t][2 * h + 1] + sbias[c + 1];
                if (relu) { v0 = fmaxf(v0, 0.f); v1 = fmaxf(v1, 0.f); }
                *(u32*)&HI[r * 264 + c] = f2h(v0) | (f2h(v1) << 16);
            }
}

__global__ void __launch_bounds__(256, 2) nerf_mma(Params p)
{
    extern __shared__ char sm[];
    u16* PHI = (u16*)(sm + O_PEHI);
    u16* DHI = (u16*)(sm + O_DEHI);
    float* sball = (float*)(sm + O_BIAS);   // all biases: L0..L8 at 256*L, r1 at 2304
    float* sdcol = (float*)(sm + O_DCOL);
    float* swr2  = (float*)(sm + O_WR2);
    float* sred  = (float*)(sm + O_PEHI);   // scratch (PE dead after layer 4)

    const int tid = threadIdx.x;
    const int l = tid & 31, wid = tid >> 5;
    const int wm = wid >> 2, wn = wid & 3;   // 2 m-groups x 4 n-groups

    // preload all biases + dcol + wr2
#pragma unroll
    for (int L = 0; L < 9; L++) sball[L * 256 + tid] = p.bias[L][tid];
    if (tid < 128) sball[2304 + tid] = p.bias[9][tid];
    sdcol[tid] = g_dcol[tid];
    for (int i = tid; i < 384; i += 256) swr2[i] = p.wr2[i];

    // posenc (one thread per point, 64 points)
    if (tid < 64) {
        const int m = tid, pt = blockIdx.x * 64 + m;
#define STP(H, STRD, COL, V) (H)[m * STRD + (COL)] = (u16)f2h(V)
        for (int d = 0; d < 3; d++) {
            float x = p.pos[pt * 3 + d];
            STP(PHI, 72, d, x);
            float f = 1.f;
#pragma unroll
            for (int q = 0; q < 10; q++) {
                float s, c; sincosf(x * f, &s, &c);
                STP(PHI, 72, 3 + 6 * q + d, s);
                STP(PHI, 72, 3 + 6 * q + 3 + d, c);
                f *= 2.f;
            }
            float y = p.dir[pt * 3 + d];
            STP(DHI, 40, d, y);
            f = 1.f;
#pragma unroll
            for (int q = 0; q < 4; q++) {
                float s, c; sincosf(y * f, &s, &c);
                STP(DHI, 40, 3 + 6 * q + d, s);
                STP(DHI, 40, 3 + 6 * q + 3 + d, c);
                f *= 2.f;
            }
        }
        STP(PHI, 72, 63, 0.f);
        for (int k = 27; k < 32; k++) STP(DHI, 40, k, 0.f);
#undef STP
    }
    __syncthreads();

    float acc[2][8][4];
#define ZACC() do { _Pragma("unroll") for (int _a = 0; _a < 2; _a++) \
    _Pragma("unroll") for (int _b = 0; _b < 8; _b++) \
    _Pragma("unroll") for (int _c = 0; _c < 4; _c++) acc[_a][_b][_c] = 0.f; } while (0)
#define ABASE(OFF, STRB) (s2u(sm) + (u32)(OFF) + (u32)((wm * 32 + (l & 15)) * (STRB) + (l >> 4) * 16))

    u32 cur = O_A0, nxt = O_A1;

    // layer 0 (pe -> A0); single sync per layer via ping-pong buffers
    ZACC();
    run_seg<8>(acc, ABASE(O_PEHI, 144), 144, 4, 32, g_w + (size_t)SEG_WIN * 32, wn, l);
    epilogue<8>(acc, (u16*)(sm + cur), sball, true, wm, wn, l);
    __syncthreads();

    // hidden layers (Wh5/Wh6 live AFTER the H4PE segment — explicit starts)
    for (int i = 0; i < 7; i++) {
        const int seg_start = (i < 5) ? (SEG_H0 + i * 512) : (SEG_H5 + (i - 5) * 512);
        ZACC();
        run_seg<8>(acc, ABASE(cur, 528), 528, 16, 32, g_w + (size_t)seg_start * 32, wn, l);
        if (i == 4)
            run_seg<8>(acc, ABASE(O_PEHI, 144), 144, 4, 32, g_w + (size_t)SEG_H4PE * 32, wn, l);
        epilogue<8>(acc, (u16*)(sm + nxt), sball + 256 * (1 + i), true, wm, wn, l);
        __syncthreads();
        u32 t = cur; cur = nxt; nxt = t;
    }

    // out layer: density partials (4 threads/point) + features MMA
    {
        const int q = tid >> 6, m = tid & 63;
        float dsum = 0.f;
        const u64* arow = (const u64*)((u16*)(sm + cur) + m * 264 + q * 64);
        const float* dc = sdcol + q * 64;
#pragma unroll
        for (int kb = 0; kb < 16; kb++) {
            u64 v = arow[kb];
            dsum += h2f((u32)(v      ) & 0xFFFF) * dc[kb * 4 + 0];
            dsum += h2f((u32)(v >> 16) & 0xFFFF) * dc[kb * 4 + 1];
            dsum += h2f((u32)(v >> 32) & 0xFFFF) * dc[kb * 4 + 2];
            dsum += h2f((u32)(v >> 48)         ) * dc[kb * 4 + 3];
        }
        sred[tid] = dsum;
    }
    ZACC();
    run_seg<8>(acc, ABASE(cur, 528), 528, 16, 32, g_w + (size_t)SEG_OUT * 32, wn, l);
    epilogue<8>(acc, (u16*)(sm + nxt), sball + 256 * 8, false, wm, wn, l);
    __syncthreads();
    { u32 t = cur; cur = nxt; nxt = t; }
    if (tid < 64)
        p.out[3 * N_PTS + blockIdx.x * 64 + tid] =
            fmaxf(sred[tid] + sred[64 + tid] + sred[128 + tid] + sred[192 + tid]
                  + p.bout[256], 0.f);

    // r1: [features, de] @ Wr1, relu, N=128
    {
        float acc4[2][4][4];
#pragma unroll
        for (int a = 0; a < 2; a++)
#pragma unroll
            for (int b = 0; b < 4; b++)
#pragma unroll
                for (int c = 0; c < 4; c++) acc4[a][b][c] = 0.f;
        run_seg<4>(acc4, ABASE(cur, 528), 528, 16, 16, g_w + (size_t)SEG_R1 * 32, wn, l);
        run_seg<4>(acc4, ABASE(O_DEHI, 80), 80, 2, 16, g_w + (size_t)SEG_R1DE * 32, wn, l);
        epilogue<4>(acc4, (u16*)(sm + nxt), sball + 2304, true, wm, wn, l);
        __syncthreads();
        u32 t = cur; cur = nxt; nxt = t;
    }

    // r2 + sigmoid: 4 threads per point, SMEM reduce
    {
        const int q = tid >> 6, m = tid & 63;
        float r0 = 0.f, r1 = 0.f, r2 = 0.f;
        const u64* arow = (const u64*)((u16*)(sm + cur) + m * 264 + q * 32);
#pragma unroll
        for (int kb = 0; kb < 8; kb++) {
            u64 v = arow[kb];
#pragma unroll
            for (int j = 0; j < 4; j++) {
                float hv = h2f((u32)(v >> (16 * j)) & 0xFFFF);
                const float* w = swr2 + (q * 32 + kb * 4 + j) * 3;
                r0 += hv * w[0]; r1 += hv * w[1]; r2 += hv * w[2];
            }
        }
        sred[tid] = r0; sred[256 + tid] = r1; sred[512 + tid] = r2;
    }
    __syncthreads();
    if (tid < 64) {
        const int pt = blockIdx.x * 64 + tid;
        float r0 = sred[tid] + sred[64 + tid] + sred[128 + tid] + sred[192 + tid] + p.br2[0];
        float r1 = sred[256 + tid] + sred[320 + tid] + sred[384 + tid] + sred[448 + tid] + p.br2[1];
        float r2 = sred[512 + tid] + sred[576 + tid] + sred[640 + tid] + sred[704 + tid] + p.br2[2];
        p.out[pt * 3 + 0] = 1.f / (1.f + expf(-r0));
        p.out[pt * 3 + 1] = 1.f / (1.f + expf(-r1));
        p.out[pt * 3 + 2] = 1.f / (1.f + expf(-r2));
    }
}

// ---------- host ----------
extern "C" void kernel_launch(void* const* d_in, const int* in_sizes, int n_in,
                              void* d_out, int out_size)
{
    const float* pos  = (const float*)d_in[0];
    const float* dir  = (const float*)d_in[1];
    const float* Win  = (const float*)d_in[2];
    const float* bin  = (const float*)d_in[3];
    const float* Wh[7]; const float* bh[7];
    for (int i = 0; i < 7; i++) { Wh[i] = (const float*)d_in[4 + 2 * i]; bh[i] = (const float*)d_in[5 + 2 * i]; }
    const float* Wout = (const float*)d_in[18];
    const float* bout = (const float*)d_in[19];
    const float* Wr1  = (const float*)d_in[20];
    const float* br1  = (const float*)d_in[21];
    const float* Wr2  = (const float*)d_in[22];
    const float* br2  = (const float*)d_in[23];

    static PrepP pp;
    pp.seg[0]  = { Win,               256, 63,  256, 32, SEG_WIN };
    for (int i = 0; i < 5; i++)
        pp.seg[1 + i] = { Wh[i],      256, 256, 256, 32, SEG_H0 + i * 512 };
    pp.seg[6]  = { Wh[4] + 256 * 256, 256, 63,  256, 32, SEG_H4PE };
    pp.seg[7]  = { Wh[5],             256, 256, 256, 32, SEG_H5 };
    pp.seg[8]  = { Wh[6],             256, 256, 256, 32, SEG_H6 };
    pp.seg[9]  = { Wout,              257, 256, 256, 32, SEG_OUT };
    pp.seg[10] = { Wr1,               128, 256, 128, 16, SEG_R1 };
    pp.seg[11] = { Wr1 + 256 * 128,   128, 27,  128, 16, SEG_R1DE };
    pp.Wout = Wout;

    static Params p;
    p.pos = pos; p.dir = dir; p.bout = bout; p.wr2 = Wr2; p.br2 = br2;
    p.bias[0] = bin;
    for (int i = 0; i < 7; i++) p.bias[1 + i] = bh[i];
    p.bias[8] = bout; p.bias[9] = br1;
    p.out = (float*)d_out;

    prep_kernel<<<TOTB / 8, 256>>>(pp);
    cudaFuncSetAttribute(nerf_mma, cudaFuncAttributeMaxDynamicSharedMemorySize, SMEM_TOTAL);
    nerf_mma<<<N_PTS / 64, 256, SMEM_TOTAL>>>(p);
}